// round 14
// baseline (speedup 1.0000x reference)
#include <cuda_runtime.h>
#include <math.h>
#include <stdint.h>

// ---------------- problem constants ----------------
#define BB     16
#define LIN    400
#define TT     100
#define DD     512
#define HH     8
#define DEPTH  64
#define DFF    2048
#define VV     32000
#define OOV    100
#define VEXT   32100          // VV + OOV
#define NL     2
#define BLIN   (BB*LIN)       // 6400
#define BT     (BB*TT)        // 1600
#define SQRTD  22.62741699796952f
#define QT     16             // query tile for attention

// ---------------- scratch (static device arrays; no allocs allowed) --------
__device__ float g_x   [BLIN*DD];   // encoder activations (full precision)
__device__ float g_xr  [BLIN*DD];   // encoder activations, rna-rounded (GEMM A)
__device__ float g_q   [BLIN*DD];
__device__ float g_a   [BLIN*DD];   // attention output (rna-rounded)
__device__ float g_big [BLIN*DFF];  // fused qkv out / ffn hidden
__device__ float g_dx  [BT*DD];     // decoder activations (full)
__device__ float g_dxr [BT*DD];     // decoder activations, rounded
__device__ float g_t2  [BT*DD];
__device__ float g_emb [BT*DD];
__device__ float g_b2  [BB*HH*TT*LIN];
__device__ float g_ctx [BT*DD];
__device__ float g_pg  [BT];
__device__ float g_pe  [LIN*DD];
__device__ float g_wp  [512*1536*3 + 512*1024];  // packed+rounded QKV/KV weights
__device__ float g_wt  [23986176];               // rounded direct-use weights

#define WP_ENC0  0
#define WP_ENC1  (512*1536)
#define WP_DSELF (2*512*1536)
#define WP_DCROSS (3*512*1536)

// g_wt float offsets
#define WT_EPROJ0 0
#define WT_EPROJ1 262144
#define WT_EFF1_0 524288
#define WT_EFF2_0 1572864
#define WT_EFF1_1 2621440
#define WT_EFF2_1 3670016
#define WT_DPROJ1 4718592
#define WT_DQ     4980736
#define WT_DPROJ2 5242880
#define WT_DFF1   5505024
#define WT_DFF2   6553600
#define WT_FINAL  7602176

__device__ __forceinline__ float rnaf(float x) {
    uint32_t u; asm("cvt.rna.tf32.f32 %0, %1;" : "=r"(u) : "f"(x));
    return __uint_as_float(u);
}
__device__ __forceinline__ void cp16(uint32_t s, const float* g) {
    asm volatile("cp.async.cg.shared.global [%0], [%1], 16;" :: "r"(s), "l"(g));
}

// ---------------- positional encoding (fp32) ----------------
__global__ void pe_kernel(float* __restrict__ pe) {
    int i = blockIdx.x * 256 + threadIdx.x;
    if (i >= LIN * DD) return;
    int s = i / DD, d = i % DD;
    const float LOG2_10000 = 13.28771237954945f;
    float rate = exp2f(-((float)(2 * (d / 2)) * (1.0f / 512.0f)) * LOG2_10000);
    float sv, cv;
    sincosf((float)s * rate, &sv, &cv);
    pe[i] = (d & 1) ? cv : sv;
}

// ---------------- merged weight packing (rounded) --------------------------
__global__ void pack_all_kernel(const float* __restrict__ eaw,
                                const float* __restrict__ daw,
                                float* __restrict__ wp)
{
    const int MAT = 512 * 512;
    int i = blockIdx.x * 256 + threadIdx.x;
    if (i >= 11 * MAT) return;
    const float* src; float* dst; int nmat, e;
    if (i < 3 * MAT)        { src = eaw;            dst = wp + WP_ENC0;   nmat = 3; e = i; }
    else if (i < 6 * MAT)   { src = eaw + 4 * MAT;  dst = wp + WP_ENC1;   nmat = 3; e = i - 3 * MAT; }
    else if (i < 9 * MAT)   { src = daw + 8 * MAT;  dst = wp + WP_DSELF;  nmat = 3; e = i - 6 * MAT; }
    else                    { src = daw + 13 * MAT; dst = wp + WP_DCROSS; nmat = 2; e = i - 9 * MAT; }
    int n = e & 511;
    int k = (e >> 9) & 511;
    int j = e >> 18;
    dst[(size_t)k * (nmat * 512) + j * 512 + n] = rnaf(src[(size_t)j * MAT + (size_t)k * 512 + n]);
}

// ---------------- rounded copies of all direct-use B matrices --------------
__global__ void rna_all_kernel(const float* __restrict__ eaw, const float* __restrict__ ew1,
                               const float* __restrict__ ew2, const float* __restrict__ daw,
                               const float* __restrict__ dw1, const float* __restrict__ dw2,
                               const float* __restrict__ fw, float* __restrict__ wt)
{
    const int MAT = 512 * 512;
    const int FF  = 512 * 2048;
    size_t i = (size_t)blockIdx.x * 256 + threadIdx.x;
    if (i >= 23986176u) return;
    const float* s; size_t e;
    if      (i < (size_t)WT_EPROJ1)              { s = eaw + 3 * MAT;  e = i; }
    else if (i < (size_t)WT_EFF1_0)              { s = eaw + 7 * MAT;  e = i - WT_EPROJ1; }
    else if (i < (size_t)WT_EFF2_0)              { s = ew1;            e = i - WT_EFF1_0; }
    else if (i < (size_t)WT_EFF1_1)              { s = ew2;            e = i - WT_EFF2_0; }
    else if (i < (size_t)WT_EFF2_1)              { s = ew1 + FF;       e = i - WT_EFF1_1; }
    else if (i < (size_t)WT_DPROJ1)              { s = ew2 + FF;       e = i - WT_EFF2_1; }
    else if (i < (size_t)WT_DQ)                  { s = daw + 11 * MAT; e = i - WT_DPROJ1; }
    else if (i < (size_t)WT_DPROJ2)              { s = daw + 12 * MAT; e = i - WT_DQ; }
    else if (i < (size_t)WT_DFF1)                { s = daw + 15 * MAT; e = i - WT_DPROJ2; }
    else if (i < (size_t)WT_DFF2)                { s = dw1 + FF;       e = i - WT_DFF1; }
    else if (i < (size_t)WT_FINAL)               { s = dw2 + FF;       e = i - WT_DFF2; }
    else                                         { s = fw;             e = i - WT_FINAL; }
    wt[i] = rnaf(s[e]);
}

// ---------------- embeddings (dual write: full + rounded) ------------------
__global__ void embed_enc_kernel(const int* __restrict__ inp,
                                 const float* __restrict__ emb,
                                 const float* __restrict__ pe,
                                 float* __restrict__ x, float* __restrict__ xr) {
    size_t i = (size_t)blockIdx.x * 256 + threadIdx.x;
    if (i >= (size_t)BLIN * DD) return;
    int d = (int)(i % DD);
    size_t tokI = i / DD;
    int s = (int)(tokI % LIN);
    float v = emb[(size_t)inp[tokI] * DD + d] * SQRTD + pe[s * DD + d];
    x[i] = v;
    xr[i] = rnaf(v);
}

__global__ void embed_dec_kernel(const int* __restrict__ tar,
                                 const float* __restrict__ emb,
                                 const float* __restrict__ pe,
                                 float* __restrict__ embout,
                                 float* __restrict__ x, float* __restrict__ xr) {
    size_t i = (size_t)blockIdx.x * 256 + threadIdx.x;
    if (i >= (size_t)BT * DD) return;
    int d = (int)(i % DD);
    size_t tokI = i / DD;
    int s = (int)(tokI % TT);
    float e = emb[(size_t)tar[tokI] * DD + d];
    embout[i] = e;
    float v = e * SQRTD + pe[s * DD + d];
    x[i] = v;
    xr[i] = rnaf(v);
}

// ---------------- TF32 tensor-core GEMM, cp.async 4-stage, NO in-loop cvt --
// All inputs are PRE-ROUNDED tf32 values; raw-bit feed == rna rounding.
#define STAGES 4
#define ASTR 20
#define BSTR 136
#define A_STAGE (128*ASTR)
#define B_STAGE (16*BSTR)
#define GEMM_SMEM ((STAGES*(A_STAGE + B_STAGE))*4)

__global__ void __launch_bounds__(256, 2) gemm_tf32_kernel(
    const float* __restrict__ A, const float* __restrict__ W,
    const float* __restrict__ bias, float* __restrict__ C,
    int M, int N, int K, int ldc,
    const float* __restrict__ rowScale, int relu, int roundOut)
{
    extern __shared__ uint32_t smemRaw[];
    uint32_t* AsBase = smemRaw;
    uint32_t* BsBase = smemRaw + STAGES * A_STAGE;

    int tid  = threadIdx.x;
    int warp = tid >> 5, lane = tid & 31;
    int g = lane >> 2, tig = lane & 3;
    int wm = warp >> 2, wn = warp & 3;
    int mWarp = wm * 64, nWarp = wn * 32;
    int rowBase = blockIdx.y * 128, colBase = blockIdx.x * 128;

    int aRow = tid >> 1;
    int aCh  = (tid & 1) * 2;
    int gRowA = rowBase + aRow; if (gRowA > M - 1) gRowA = M - 1;
    const float* Aload = A + (size_t)gRowA * K + aCh * 4;
    uint32_t aOff = (uint32_t)(aRow * ASTR + aCh * 4);

    int bRow = tid >> 4;
    int bC   = tid & 15;
    const float* Bload = W + (size_t)bRow * N + colBase + bC * 4;
    uint32_t bOff = (uint32_t)(bRow * BSTR + bC * 4);

    uint32_t aSm[STAGES], bSm[STAGES];
#pragma unroll
    for (int s = 0; s < STAGES; s++) {
        aSm[s] = (uint32_t)__cvta_generic_to_shared(AsBase + s * A_STAGE + aOff);
        bSm[s] = (uint32_t)__cvta_generic_to_shared(BsBase + s * B_STAGE + bOff);
    }

    int KT = K / 16;

#pragma unroll
    for (int s = 0; s < STAGES - 1; s++) {
        if (s < KT) {
            const float* Ap = Aload + s * 16;
            cp16(aSm[s], Ap);
            cp16(aSm[s] + 16, Ap + 4);
            const float* Bp = Bload + (size_t)s * 16 * N;
            cp16(bSm[s], Bp);
            cp16(bSm[s] + 256, Bp + 64);
        }
        asm volatile("cp.async.commit_group;");
    }

    float acc[4][4][4];
#pragma unroll
    for (int i = 0; i < 4; i++)
#pragma unroll
        for (int j = 0; j < 4; j++)
#pragma unroll
            for (int r = 0; r < 4; r++) acc[i][j][r] = 0.f;

    for (int kt = 0; kt < KT; kt++) {
        asm volatile("cp.async.wait_group %0;" :: "n"(STAGES - 2));
        __syncthreads();

        {
            int kn = kt + STAGES - 1;
            int sn = kn % STAGES;
            if (kn < KT) {
                const float* Ap = Aload + (size_t)kn * 16;
                cp16(aSm[sn], Ap);
                cp16(aSm[sn] + 16, Ap + 4);
                const float* Bp = Bload + (size_t)kn * 16 * N;
                cp16(bSm[sn], Bp);
                cp16(bSm[sn] + 256, Bp + 64);
            }
            asm volatile("cp.async.commit_group;");
        }

        int st = kt % STAGES;
        const uint32_t* uA = AsBase + st * A_STAGE;
        const uint32_t* uB = BsBase + st * B_STAGE;

#pragma unroll
        for (int ks = 0; ks < 2; ks++) {
            int k = ks * 8;
            uint32_t af[4][4], bf[4][2];
#pragma unroll
            for (int mt = 0; mt < 4; mt++) {
                int m0 = mWarp + mt * 16 + g;
                af[mt][0] = uA[m0 * ASTR + k + tig];
                af[mt][1] = uA[(m0 + 8) * ASTR + k + tig];
                af[mt][2] = uA[m0 * ASTR + k + tig + 4];
                af[mt][3] = uA[(m0 + 8) * ASTR + k + tig + 4];
            }
#pragma unroll
            for (int nt = 0; nt < 4; nt++) {
                int n0 = nWarp + nt * 8 + g;
                bf[nt][0] = uB[(k + tig) * BSTR + n0];
                bf[nt][1] = uB[(k + tig + 4) * BSTR + n0];
            }
#pragma unroll
            for (int mt = 0; mt < 4; mt++)
#pragma unroll
                for (int nt = 0; nt < 4; nt++) {
                    asm volatile(
                        "mma.sync.aligned.m16n8k8.row.col.f32.tf32.tf32.f32 "
                        "{%0,%1,%2,%3}, {%4,%5,%6,%7}, {%8,%9}, {%0,%1,%2,%3};"
                        : "+f"(acc[mt][nt][0]), "+f"(acc[mt][nt][1]),
                          "+f"(acc[mt][nt][2]), "+f"(acc[mt][nt][3])
                        : "r"(af[mt][0]), "r"(af[mt][1]), "r"(af[mt][2]), "r"(af[mt][3]),
                          "r"(bf[nt][0]), "r"(bf[nt][1]));
                }
        }
    }

#pragma unroll
    for (int mt = 0; mt < 4; mt++) {
#pragma unroll
        for (int half = 0; half < 2; half++) {
            int r = rowBase + mWarp + mt * 16 + g + half * 8;
            if (r >= M) continue;
            float s = rowScale ? rowScale[r] : 1.0f;
#pragma unroll
            for (int nt = 0; nt < 4; nt++) {
                int c = colBase + nWarp + nt * 8 + tig * 2;
                float v0 = acc[mt][nt][half * 2 + 0] + bias[c];
                float v1 = acc[mt][nt][half * 2 + 1] + bias[c + 1];
                if (relu) { v0 = fmaxf(v0, 0.f); v1 = fmaxf(v1, 0.f); }
                v0 *= s; v1 *= s;
                if (roundOut) { v0 = rnaf(v0); v1 = rnaf(v1); }
                *reinterpret_cast<float2*>(&C[(size_t)r * ldc + c]) = make_float2(v0, v1);
            }
        }
    }
}

// ---------------- tiled fused attention (rounded output) ----------------
__global__ void __launch_bounds__(128) attn_tile_kernel(
    const float* __restrict__ q, const float* __restrict__ k,
    const float* __restrict__ v, float* __restrict__ out,
    float* __restrict__ attn_save, int Sq, int Sk, int causal,
    int ldq, int ldk, int ldv)
{
    __shared__ float qs[QT][DEPTH];
    __shared__ float sc[QT][LIN];
    __shared__ float pvs[2][QT][DEPTH];

    int qt0 = blockIdx.x * QT, h = blockIdx.y, b = blockIdx.z;
    int tid = threadIdx.x;

    for (int e = tid; e < QT * DEPTH; e += 128) {
        int qr = e >> 6, d = e & 63;
        int qg = qt0 + qr;
        qs[qr][d] = (qg < Sq) ? q[((size_t)(b * Sq + qg)) * ldq + h * DEPTH + d] : 0.f;
    }
    __syncthreads();

    for (int j = tid; j < Sk; j += 128) {
        const float* krow = k + ((size_t)(b * Sk + j)) * ldk + h * DEPTH;
        float acc[QT];
#pragma unroll
        for (int qr = 0; qr < QT; qr++) acc[qr] = 0.f;
#pragma unroll
        for (int c = 0; c < DEPTH / 4; c++) {
            float4 k4 = *reinterpret_cast<const float4*>(krow + c * 4);
#pragma unroll
            for (int qr = 0; qr < QT; qr++) {
                float4 q4 = *reinterpret_cast<const float4*>(&qs[qr][c * 4]);
                acc[qr] += q4.x * k4.x + q4.y * k4.y + q4.z * k4.z + q4.w * k4.w;
            }
        }
#pragma unroll
        for (int qr = 0; qr < QT; qr++) {
            float s = acc[qr] * 0.125f;
            if (causal && j > qt0 + qr) s -= 1e9f;
            sc[qr][j] = s;
        }
    }
    __syncthreads();

    {
        int warp = tid >> 5, lane = tid & 31;
        for (int qr = warp; qr < QT; qr += 4) {
            int qg = qt0 + qr;
            if (qg >= Sq) continue;
            float mx = -1e30f;
            for (int j = lane; j < Sk; j += 32) mx = fmaxf(mx, sc[qr][j]);
#pragma unroll
            for (int o = 16; o > 0; o >>= 1) mx = fmaxf(mx, __shfl_xor_sync(0xffffffffu, mx, o));
            float sum = 0.f;
            for (int j = lane; j < Sk; j += 32) {
                float e = __expf(sc[qr][j] - mx);
                sc[qr][j] = e;
                sum += e;
            }
#pragma unroll
            for (int o = 16; o > 0; o >>= 1) sum += __shfl_xor_sync(0xffffffffu, sum, o);
            float inv = 1.f / sum;
            for (int j = lane; j < Sk; j += 32) {
                float p = sc[qr][j] * inv;
                sc[qr][j] = p;
                if (attn_save)
                    attn_save[(((size_t)(b * HH + h)) * Sq + qg) * Sk + j] = p;
            }
        }
    }
    __syncthreads();

    {
        int gg = tid >> 6, d = tid & 63;
        float acc[QT];
#pragma unroll
        for (int qr = 0; qr < QT; qr++) acc[qr] = 0.f;
        for (int j = gg; j < Sk; j += 2) {
            float vv = v[((size_t)(b * Sk + j)) * ldv + h * DEPTH + d];
#pragma unroll
            for (int qr = 0; qr < QT; qr++) acc[qr] += sc[qr][j] * vv;
        }
#pragma unroll
        for (int qr = 0; qr < QT; qr++) pvs[gg][qr][d] = acc[qr];
    }
    __syncthreads();

    for (int e = tid; e < QT * DEPTH; e += 128) {
        int qr = e >> 6, d = e & 63;
        int qg = qt0 + qr;
        if (qg < Sq)   // rounded: consumed only as GEMM A operand
            out[((size_t)(b * Sq + qg)) * DD + h * DEPTH + d] = rnaf(pvs[0][qr][d] + pvs[1][qr][d]);
    }
}

// ---------------- residual + LayerNorm (dual write: full + rounded) --------
__global__ void __launch_bounds__(256) ln_kernel(
    float* __restrict__ x, const float* __restrict__ r,
    const float* __restrict__ g, const float* __restrict__ b,
    float* __restrict__ xr)
{
    __shared__ float sm[8];
    __shared__ float bc;
    int row = blockIdx.x, tid = threadIdx.x;
    size_t base = (size_t)row * DD;
    float v0 = x[base + tid] + r[base + tid];
    float v1 = x[base + tid + 256] + r[base + tid + 256];
    float s = v0 + v1;
#pragma unroll
    for (int o = 16; o > 0; o >>= 1) s += __shfl_xor_sync(0xffffffffu, s, o);
    if ((tid & 31) == 0) sm[tid >> 5] = s;
    __syncthreads();
    if (tid == 0) {
        float t = 0.f;
        for (int w = 0; w < 8; w++) t += sm[w];
        bc = t * (1.0f / DD);
    }
    __syncthreads();
    float mean = bc;
    float d0 = v0 - mean, d1 = v1 - mean;
    float s2 = d0 * d0 + d1 * d1;
#pragma unroll
    for (int o = 16; o > 0; o >>= 1) s2 += __shfl_xor_sync(0xffffffffu, s2, o);
    if ((tid & 31) == 0) sm[tid >> 5] = s2;
    __syncthreads();
    if (tid == 0) {
        float t = 0.f;
        for (int w = 0; w < 8; w++) t += sm[w];
        bc = rsqrtf(t * (1.0f / DD) + 1e-6f);
    }
    __syncthreads();
    float inv = bc;
    float o0 = d0 * inv * g[tid]       + b[tid];
    float o1 = d1 * inv * g[tid + 256] + b[tid + 256];
    x[base + tid]       = o0;
    x[base + tid + 256] = o1;
    xr[base + tid]       = rnaf(o0);
    xr[base + tid + 256] = rnaf(o1);
}

// ---------------- tiled context ----------------
__global__ void __launch_bounds__(128) context_tile_kernel(
    const float* __restrict__ attn, const float* __restrict__ enc,
    float* __restrict__ ctx)
{
    __shared__ float at[QT][LIN];
    __shared__ float pvs[2][QT][DEPTH];

    int tt0 = blockIdx.x * QT, h = blockIdx.y, b = blockIdx.z;
    int tid = threadIdx.x;

    for (int e = tid; e < QT * LIN; e += 128) {
        int tr = e / LIN, l = e % LIN;
        int tg = tt0 + tr;
        at[tr][l] = (tg < TT)
            ? attn[(((size_t)(b * HH + h)) * TT + tg) * LIN + l] : 0.f;
    }
    __syncthreads();

    int g = tid >> 6, d = tid & 63;
    float acc[QT];
#pragma unroll
    for (int tr = 0; tr < QT; tr++) acc[tr] = 0.f;
    for (int l = g; l < LIN; l += 2) {
        float ev = enc[((size_t)(b * LIN + l)) * DD + h * DEPTH + d];
#pragma unroll
        for (int tr = 0; tr < QT; tr++) acc[tr] += at[tr][l] * ev;
    }
#pragma unroll
    for (int tr = 0; tr < QT; tr++) pvs[g][tr][d] = acc[tr];
    __syncthreads();

    for (int e = tid; e < QT * DEPTH; e += 128) {
        int tr = e >> 6, dd = e & 63;
        int tg = tt0 + tr;
        if (tg < TT)
            ctx[((size_t)(b * TT + tg)) * DD + h * DEPTH + dd] = pvs[0][tr][dd] + pvs[1][tr][dd];
    }
}

__global__ void __launch_bounds__(128) pgen_kernel(
    const float* __restrict__ ctx, const float* __restrict__ dec,
    const float* __restrict__ emb, const float* __restrict__ pw,
    const float* __restrict__ pb, float* __restrict__ pg)
{
    __shared__ float sm[4];
    int row = blockIdx.x, tid = threadIdx.x;
    size_t base = (size_t)row * DD;
    float s = 0.f;
    for (int d = tid; d < DD; d += 128)
        s += ctx[base + d] * pw[d] + dec[base + d] * pw[DD + d] + emb[base + d] * pw[2 * DD + d];
#pragma unroll
    for (int o = 16; o > 0; o >>= 1) s += __shfl_xor_sync(0xffffffffu, s, o);
    if ((tid & 31) == 0) sm[tid >> 5] = s;
    __syncthreads();
    if (tid == 0) {
        float t = sm[0] + sm[1] + sm[2] + sm[3] + pb[0] + pb[1] + pb[2];
        pg[row] = 1.0f / (1.0f + expf(-t));
    }
}

__global__ void attnmean_kernel(const float* __restrict__ b2, float* __restrict__ outm) {
    size_t i = (size_t)blockIdx.x * 256 + threadIdx.x;
    if (i >= (size_t)BT * LIN) return;
    int l = (int)(i % LIN);
    int t = (int)((i / LIN) % TT);
    int b = (int)(i / ((size_t)LIN * TT));
    float s = 0.f;
    for (int h = 0; h < HH; h++)
        s += b2[(((size_t)(b * HH + h)) * TT + t) * LIN + l];
    outm[i] = s * 0.125f;
}

__global__ void zerotail_kernel(float* __restrict__ out) {
    int i = blockIdx.x * 256 + threadIdx.x;
    if (i >= BT * OOV) return;
    int row = i / OOV, c = i % OOV;
    out[(size_t)row * VEXT + VV + c] = 0.f;
}

__global__ void scatter_kernel(const float* __restrict__ am, const float* __restrict__ pg,
                               const int* __restrict__ ext, float* __restrict__ out) {
    size_t i = (size_t)blockIdx.x * 256 + threadIdx.x;
    if (i >= (size_t)BT * LIN) return;
    int l = (int)(i % LIN);
    int t = (int)((i / LIN) % TT);
    int b = (int)(i / ((size_t)LIN * TT));
    int idx = ext[b * LIN + l];
    float val = (1.0f - pg[b * TT + t]) * am[i];
    atomicAdd(&out[((size_t)(b * TT) + t) * VEXT + idx], val);
}

// ---------------- host orchestration ----------------
static inline void gemm(const float* A, const float* W, const float* bias, float* C,
                        int M, int N, int K, int ldc, const float* rowScale,
                        int relu, int roundOut) {
    dim3 grid(N / 128, (M + 127) / 128);
    gemm_tf32_kernel<<<grid, 256, GEMM_SMEM>>>(A, W, bias, C, M, N, K, ldc,
                                               rowScale, relu, roundOut);
}

extern "C" void kernel_launch(void* const* d_in, const int* in_sizes, int n_in,
                              void* d_out, int out_size)
{
    const int* inp = (const int*)d_in[0];
    const int* tar = (const int*)d_in[1];
    const int* ext = (const int*)d_in[2];
    int wi = (in_sizes[6] == 1) ? 7 : 6;
    const float* emb_enc = (const float*)d_in[wi + 0];
    const float* emb_dec = (const float*)d_in[wi + 1];
    const float* eaw = (const float*)d_in[wi + 2];
    const float* eab = (const float*)d_in[wi + 3];
    const float* ew1 = (const float*)d_in[wi + 4];
    const float* eb1 = (const float*)d_in[wi + 5];
    const float* ew2 = (const float*)d_in[wi + 6];
    const float* eb2 = (const float*)d_in[wi + 7];
    const float* elg = (const float*)d_in[wi + 8];
    const float* elb = (const float*)d_in[wi + 9];
    const float* daw = (const float*)d_in[wi + 10];
    const float* dab = (const float*)d_in[wi + 11];
    const float* dw1 = (const float*)d_in[wi + 12];
    const float* db1 = (const float*)d_in[wi + 13];
    const float* dw2 = (const float*)d_in[wi + 14];
    const float* db2 = (const float*)d_in[wi + 15];
    const float* dlg = (const float*)d_in[wi + 16];
    const float* dlb = (const float*)d_in[wi + 17];
    const float* ptw = (const float*)d_in[wi + 18];
    const float* ptb = (const float*)d_in[wi + 19];
    const float* fw  = (const float*)d_in[wi + 20];
    const float* fb  = (const float*)d_in[wi + 21];
    float* out = (float*)d_out;

    cudaFuncSetAttribute(gemm_tf32_kernel,
                         cudaFuncAttributeMaxDynamicSharedMemorySize, GEMM_SMEM);

    float *xp, *xrp, *qp, *ap, *bigp, *dxp, *dxrp, *t2p, *embp, *b2p, *ctxp, *pgp, *pep, *wpp, *wtp;
    cudaGetSymbolAddress((void**)&xp,   g_x);
    cudaGetSymbolAddress((void**)&xrp,  g_xr);
    cudaGetSymbolAddress((void**)&qp,   g_q);
    cudaGetSymbolAddress((void**)&ap,   g_a);
    cudaGetSymbolAddress((void**)&bigp, g_big);
    cudaGetSymbolAddress((void**)&dxp,  g_dx);
    cudaGetSymbolAddress((void**)&dxrp, g_dxr);
    cudaGetSymbolAddress((void**)&t2p,  g_t2);
    cudaGetSymbolAddress((void**)&embp, g_emb);
    cudaGetSymbolAddress((void**)&b2p,  g_b2);
    cudaGetSymbolAddress((void**)&ctxp, g_ctx);
    cudaGetSymbolAddress((void**)&pgp,  g_pg);
    cudaGetSymbolAddress((void**)&pep,  g_pe);
    cudaGetSymbolAddress((void**)&wpp,  g_wp);
    cudaGetSymbolAddress((void**)&wtp,  g_wt);

    // launches 0-3 (keeps the fused QKV gemm at the ncu-profiled slot)
    pe_kernel<<<(LIN * DD + 255) / 256, 256>>>(pep);
    embed_enc_kernel<<<((size_t)BLIN * DD + 255) / 256, 256>>>(inp, emb_enc, pep, xp, xrp);
    pack_all_kernel<<<(11 * 512 * 512 + 255) / 256, 256>>>(eaw, daw, wpp);
    rna_all_kernel<<<(23986176 + 255) / 256, 256>>>(eaw, ew1, ew2, daw, dw1, dw2, fw, wtp);

    // ---------- encoder ----------
    for (int i = 0; i < NL; i++) {
        gemm(xrp, wpp + (i == 0 ? WP_ENC0 : WP_ENC1), eab + (i * 4 + 0) * DD, bigp,
             BLIN, 1536, DD, 1536, nullptr, 0, 0);
        attn_tile_kernel<<<dim3(LIN / QT, HH, BB), 128>>>(
            bigp, bigp + 512, bigp + 1024, ap, nullptr, LIN, LIN, 0, 1536, 1536, 1536);
        gemm(ap, wtp + (i == 0 ? WT_EPROJ0 : WT_EPROJ1), eab + (i * 4 + 3) * DD, qp,
             BLIN, DD, DD, DD, nullptr, 0, 0);
        ln_kernel<<<BLIN, 256>>>(xp, qp, elg + (i * 2 + 0) * DD, elb + (i * 2 + 0) * DD, xrp);
        gemm(xrp, wtp + (i == 0 ? WT_EFF1_0 : WT_EFF1_1), eb1 + i * DFF, bigp,
             BLIN, DFF, DD, DFF, nullptr, 1, 1);
        gemm(bigp, wtp + (i == 0 ? WT_EFF2_0 : WT_EFF2_1), eb2 + i * DD, qp,
             BLIN, DD, DFF, DD, nullptr, 0, 0);
        ln_kernel<<<BLIN, 256>>>(xp, qp, elg + (i * 2 + 1) * DD, elb + (i * 2 + 1) * DD, xrp);
    }
    // xp = enc_output (full), xrp = rounded enc_output

    // ---------- decoder (only last layer matters; reference never chains) --
    embed_dec_kernel<<<((size_t)BT * DD + 255) / 256, 256>>>(tar, emb_dec, pep, embp, dxp, dxrp);
    {
        const int i = NL - 1;
        const int TQ = (TT + QT - 1) / QT;
        gemm(dxrp, wpp + WP_DSELF, dab + ((i * 2 + 0) * 4 + 0) * DD, bigp,
             BT, 1536, DD, 1536, nullptr, 0, 0);
        attn_tile_kernel<<<dim3(TQ, HH, BB), 128>>>(
            bigp, bigp + 512, bigp + 1024, ap, nullptr, TT, TT, 1, 1536, 1536, 1536);
        gemm(ap, wtp + WT_DPROJ1, dab + ((i * 2 + 0) * 4 + 3) * DD, t2p, BT, DD, DD, DD, nullptr, 0, 0);
        ln_kernel<<<BT, 256>>>(dxp, t2p, dlg + (i * 3 + 0) * DD, dlb + (i * 3 + 0) * DD, dxrp);  // o1
        gemm(dxrp, wtp + WT_DQ, dab + ((i * 2 + 1) * 4 + 0) * DD, qp, BT, DD, DD, DD, nullptr, 0, 0);
        gemm(xrp, wpp + WP_DCROSS, dab + ((i * 2 + 1) * 4 + 1) * DD, bigp,
             BLIN, 1024, DD, 1024, nullptr, 0, 0);
        attn_tile_kernel<<<dim3(TQ, HH, BB), 128>>>(
            qp, bigp, bigp + 512, ap, b2p, TT, LIN, 0, 512, 1024, 1024);
        gemm(ap, wtp + WT_DPROJ2, dab + ((i * 2 + 1) * 4 + 3) * DD, t2p, BT, DD, DD, DD, nullptr, 0, 0);
        ln_kernel<<<BT, 256>>>(dxp, t2p, dlg + (i * 3 + 1) * DD, dlb + (i * 3 + 1) * DD, dxrp);  // o2
        gemm(dxrp, wtp + WT_DFF1, db1 + i * DFF, bigp, BT, DFF, DD, DFF, nullptr, 1, 1);
        gemm(bigp, wtp + WT_DFF2, db2 + i * DD, t2p, BT, DD, DFF, DD, nullptr, 0, 0);
        ln_kernel<<<BT, 256>>>(dxp, t2p, dlg + (i * 3 + 2) * DD, dlb + (i * 3 + 2) * DD, dxrp);  // dec_out
    }

    // ---------- pointer-generator head ----------
    const size_t OUT2 = (size_t)BT * VEXT;
    context_tile_kernel<<<dim3((TT + QT - 1) / QT, HH, BB), 128>>>(b2p, xp, ctxp);
    pgen_kernel<<<BT, 128>>>(ctxp, dxp, embp, ptw, ptb, pgp);
    attnmean_kernel<<<((size_t)BT * LIN + 255) / 256, 256>>>(b2p, out + OUT2);
    gemm(dxrp, wtp + WT_FINAL, fb, out, BT, VV, DD, VEXT, pgp, 0, 0);
    zerotail_kernel<<<(BT * OOV + 255) / 256, 256>>>(out);
    scatter_kernel<<<((size_t)BT * LIN + 255) / 256, 256>>>(out + OUT2, pgp, ext, out);
}

// round 15
// speedup vs baseline: 1.0761x; 1.0761x over previous
#include <cuda_runtime.h>
#include <math.h>
#include <stdint.h>

// ---------------- problem constants ----------------
#define BB     16
#define LIN    400
#define TT     100
#define DD     512
#define HH     8
#define DEPTH  64
#define DFF    2048
#define VV     32000
#define OOV    100
#define VEXT   32100          // VV + OOV
#define NL     2
#define BLIN   (BB*LIN)       // 6400
#define BT     (BB*TT)        // 1600
#define SQRTD  22.62741699796952f
#define QT     16             // query tile for attention

// ---------------- scratch (static device arrays; no allocs allowed) --------
__device__ float g_x   [BLIN*DD];   // encoder activations / enc_output
__device__ float g_q   [BLIN*DD];
__device__ float g_a   [BLIN*DD];   // attention output
__device__ float g_big [BLIN*DFF];  // fused qkv / ffn hidden
__device__ float g_dx  [BT*DD];     // decoder activations (in-place LN)
__device__ float g_t2  [BT*DD];     // decoder temp
__device__ float g_emb [BT*DD];     // raw decoder embedding (for p_gen)
__device__ float g_b2  [BB*HH*TT*LIN]; // cross-attn probs
__device__ float g_ctx [BT*DD];
__device__ float g_pg  [BT];
__device__ float g_pe  [LIN*DD];    // positional encoding
__device__ float g_wp  [512*1536*3 + 512*1024];  // packed QKV / KV weights

#define WP_ENC0  0
#define WP_ENC1  (512*1536)
#define WP_DSELF (2*512*1536)
#define WP_DCROSS (3*512*1536)

// ---------------- positional encoding (fp32) ----------------
__global__ void pe_kernel(float* __restrict__ pe) {
    int i = blockIdx.x * 256 + threadIdx.x;
    if (i >= LIN * DD) return;
    int s = i / DD, d = i % DD;
    const float LOG2_10000 = 13.28771237954945f;
    float rate = exp2f(-((float)(2 * (d / 2)) * (1.0f / 512.0f)) * LOG2_10000);
    float sv, cv;
    sincosf((float)s * rate, &sv, &cv);
    pe[i] = (d & 1) ? cv : sv;
}

// ---------------- merged weight packing (single launch) --------------------
__global__ void pack_all_kernel(const float* __restrict__ eaw,
                                const float* __restrict__ daw,
                                float* __restrict__ wp)
{
    const int MAT = 512 * 512;
    int i = blockIdx.x * 256 + threadIdx.x;
    if (i >= 11 * MAT) return;
    const float* src; float* dst; int nmat, e;
    if (i < 3 * MAT)        { src = eaw;            dst = wp + WP_ENC0;   nmat = 3; e = i; }
    else if (i < 6 * MAT)   { src = eaw + 4 * MAT;  dst = wp + WP_ENC1;   nmat = 3; e = i - 3 * MAT; }
    else if (i < 9 * MAT)   { src = daw + 8 * MAT;  dst = wp + WP_DSELF;  nmat = 3; e = i - 6 * MAT; }
    else                    { src = daw + 13 * MAT; dst = wp + WP_DCROSS; nmat = 2; e = i - 9 * MAT; }
    int n = e & 511;
    int k = (e >> 9) & 511;
    int j = e >> 18;
    dst[(size_t)k * (nmat * 512) + j * 512 + n] = src[(size_t)j * MAT + (size_t)k * 512 + n];
}

// ---------------- embeddings ----------------
__global__ void embed_enc_kernel(const int* __restrict__ inp,
                                 const float* __restrict__ emb,
                                 const float* __restrict__ pe,
                                 float* __restrict__ x) {
    size_t i = (size_t)blockIdx.x * 256 + threadIdx.x;
    if (i >= (size_t)BLIN * DD) return;
    int d = (int)(i % DD);
    size_t tokI = i / DD;
    int s = (int)(tokI % LIN);
    x[i] = emb[(size_t)inp[tokI] * DD + d] * SQRTD + pe[s * DD + d];
}

__global__ void embed_dec_kernel(const int* __restrict__ tar,
                                 const float* __restrict__ emb,
                                 const float* __restrict__ pe,
                                 float* __restrict__ embout,
                                 float* __restrict__ x) {
    size_t i = (size_t)blockIdx.x * 256 + threadIdx.x;
    if (i >= (size_t)BT * DD) return;
    int d = (int)(i % DD);
    size_t tokI = i / DD;
    int s = (int)(tokI % TT);
    float e = emb[(size_t)tar[tokI] * DD + d];
    embout[i] = e;
    x[i] = e * SQRTD + pe[s * DD + d];
}

// ---------------- TF32 tensor-core GEMM, cp.async 3-stage, BM=64 ----------
// C[M,ldc] = act(A[M,K] @ W[K,N] + bias) * rowScale
// BM=64, BN=128, BK=16, 256 threads = 8 warps (2x4), warp tile 32x32.
// 3 CTAs/SM (regs ~80): 24 warps/SM to hide smem->mma latency.
// cvt.rna.tf32 on the fragment path (round-5/13 numerics, PROVEN passing).
#define STAGES 3
#define ASTR 20
#define BSTR 136
#define A_STAGE (64*ASTR)
#define B_STAGE (16*BSTR)
#define GEMM_SMEM ((STAGES*(A_STAGE + B_STAGE))*4)

__device__ __forceinline__ void cp16(uint32_t s, const float* g) {
    asm volatile("cp.async.cg.shared.global [%0], [%1], 16;" :: "r"(s), "l"(g));
}
__device__ __forceinline__ uint32_t f2tf32(float f) {
    uint32_t r;
    asm("cvt.rna.tf32.f32 %0, %1;" : "=r"(r) : "f"(f));
    return r;
}

__global__ void __launch_bounds__(256, 3) gemm_tf32_kernel(
    const float* __restrict__ A, const float* __restrict__ W,
    const float* __restrict__ bias, float* __restrict__ C,
    int M, int N, int K, int ldc,
    const float* __restrict__ rowScale, int relu)
{
    extern __shared__ uint32_t smemRaw[];
    uint32_t* AsBase = smemRaw;
    uint32_t* BsBase = smemRaw + STAGES * A_STAGE;

    int tid  = threadIdx.x;
    int warp = tid >> 5, lane = tid & 31;
    int g = lane >> 2, tig = lane & 3;
    int wm = warp >> 2, wn = warp & 3;          // 2 x 4 warp grid
    int mWarp = wm * 32, nWarp = wn * 32;       // warp tile 32x32
    int rowBase = blockIdx.y * 64, colBase = blockIdx.x * 128;

    // A loader: 64 rows x 4 float4 = 256 granules -> 1 per thread
    int aRow = tid >> 2;                // 0..63
    int aCh  = tid & 3;                 // 0..3
    int gRowA = rowBase + aRow; if (gRowA > M - 1) gRowA = M - 1;
    const float* Aload = A + (size_t)gRowA * K + aCh * 4;
    uint32_t aOff = (uint32_t)(aRow * ASTR + aCh * 4);

    // B loader: 16 krows x 32 float4 = 512 granules -> 2 per thread
    int bRow = tid >> 4;                // 0..15
    int bC   = tid & 15;                // 0..15 (chunks bC and bC+16)
    const float* Bload = W + (size_t)bRow * N + colBase + bC * 4;
    uint32_t bOff = (uint32_t)(bRow * BSTR + bC * 4);

    uint32_t aSm[STAGES], bSm[STAGES];
#pragma unroll
    for (int s = 0; s < STAGES; s++) {
        aSm[s] = (uint32_t)__cvta_generic_to_shared(AsBase + s * A_STAGE + aOff);
        bSm[s] = (uint32_t)__cvta_generic_to_shared(BsBase + s * B_STAGE + bOff);
    }

    int KT = K / 16;

#pragma unroll
    for (int s = 0; s < STAGES - 1; s++) {
        const float* Ap = Aload + s * 16;
        cp16(aSm[s], Ap);
        const float* Bp = Bload + (size_t)s * 16 * N;
        cp16(bSm[s], Bp);
        cp16(bSm[s] + 256, Bp + 64);
        asm volatile("cp.async.commit_group;");
    }

    float acc[2][4][4];
#pragma unroll
    for (int i = 0; i < 2; i++)
#pragma unroll
        for (int j = 0; j < 4; j++)
#pragma unroll
            for (int r = 0; r < 4; r++) acc[i][j][r] = 0.f;

    for (int kt = 0; kt < KT; kt++) {
        asm volatile("cp.async.wait_group %0;" :: "n"(STAGES - 2));
        __syncthreads();

        {
            int kn = kt + STAGES - 1;
            int sn = kn % STAGES;
            if (kn < KT) {
                const float* Ap = Aload + (size_t)kn * 16;
                cp16(aSm[sn], Ap);
                const float* Bp = Bload + (size_t)kn * 16 * N;
                cp16(bSm[sn], Bp);
                cp16(bSm[sn] + 256, Bp + 64);
            }
            asm volatile("cp.async.commit_group;");
        }

        int st = kt % STAGES;
        const float* fA = reinterpret_cast<const float*>(AsBase + st * A_STAGE);
        const float* fB = reinterpret_cast<const float*>(BsBase + st * B_STAGE);

#pragma unroll
        for (int ks = 0; ks < 2; ks++) {
            int k = ks * 8;
            uint32_t af[2][4], bf[4][2];
#pragma unroll
            for (int mt = 0; mt < 2; mt++) {
                int m0 = mWarp + mt * 16 + g;
                af[mt][0] = f2tf32(fA[m0 * ASTR + k + tig]);
                af[mt][1] = f2tf32(fA[(m0 + 8) * ASTR + k + tig]);
                af[mt][2] = f2tf32(fA[m0 * ASTR + k + tig + 4]);
                af[mt][3] = f2tf32(fA[(m0 + 8) * ASTR + k + tig + 4]);
            }
#pragma unroll
            for (int nt = 0; nt < 4; nt++) {
                int n0 = nWarp + nt * 8 + g;
                bf[nt][0] = f2tf32(fB[(k + tig) * BSTR + n0]);
                bf[nt][1] = f2tf32(fB[(k + tig + 4) * BSTR + n0]);
            }
#pragma unroll
            for (int mt = 0; mt < 2; mt++)
#pragma unroll
                for (int nt = 0; nt < 4; nt++) {
                    asm volatile(
                        "mma.sync.aligned.m16n8k8.row.col.f32.tf32.tf32.f32 "
                        "{%0,%1,%2,%3}, {%4,%5,%6,%7}, {%8,%9}, {%0,%1,%2,%3};"
                        : "+f"(acc[mt][nt][0]), "+f"(acc[mt][nt][1]),
                          "+f"(acc[mt][nt][2]), "+f"(acc[mt][nt][3])
                        : "r"(af[mt][0]), "r"(af[mt][1]), "r"(af[mt][2]), "r"(af[mt][3]),
                          "r"(bf[nt][0]), "r"(bf[nt][1]));
                }
        }
    }

#pragma unroll
    for (int mt = 0; mt < 2; mt++) {
#pragma unroll
        for (int half = 0; half < 2; half++) {
            int r = rowBase + mWarp + mt * 16 + g + half * 8;
            if (r >= M) continue;
            float s = rowScale ? rowScale[r] : 1.0f;
#pragma unroll
            for (int nt = 0; nt < 4; nt++) {
                int c = colBase + nWarp + nt * 8 + tig * 2;
                float v0 = acc[mt][nt][half * 2 + 0] + bias[c];
                float v1 = acc[mt][nt][half * 2 + 1] + bias[c + 1];
                if (relu) { v0 = fmaxf(v0, 0.f); v1 = fmaxf(v1, 0.f); }
                float2 o = make_float2(v0 * s, v1 * s);
                *reinterpret_cast<float2*>(&C[(size_t)r * ldc + c]) = o;
            }
        }
    }
}

// ---------------- tiled fused attention (strided q/k/v) ----------------
__global__ void __launch_bounds__(128) attn_tile_kernel(
    const float* __restrict__ q, const float* __restrict__ k,
    const float* __restrict__ v, float* __restrict__ out,
    float* __restrict__ attn_save, int Sq, int Sk, int causal,
    int ldq, int ldk, int ldv)
{
    __shared__ float qs[QT][DEPTH];
    __shared__ float sc[QT][LIN];
    __shared__ float pvs[2][QT][DEPTH];

    int qt0 = blockIdx.x * QT, h = blockIdx.y, b = blockIdx.z;
    int tid = threadIdx.x;

    for (int e = tid; e < QT * DEPTH; e += 128) {
        int qr = e >> 6, d = e & 63;
        int qg = qt0 + qr;
        qs[qr][d] = (qg < Sq) ? q[((size_t)(b * Sq + qg)) * ldq + h * DEPTH + d] : 0.f;
    }
    __syncthreads();

    for (int j = tid; j < Sk; j += 128) {
        const float* krow = k + ((size_t)(b * Sk + j)) * ldk + h * DEPTH;
        float acc[QT];
#pragma unroll
        for (int qr = 0; qr < QT; qr++) acc[qr] = 0.f;
#pragma unroll
        for (int c = 0; c < DEPTH / 4; c++) {
            float4 k4 = *reinterpret_cast<const float4*>(krow + c * 4);
#pragma unroll
            for (int qr = 0; qr < QT; qr++) {
                float4 q4 = *reinterpret_cast<const float4*>(&qs[qr][c * 4]);
                acc[qr] += q4.x * k4.x + q4.y * k4.y + q4.z * k4.z + q4.w * k4.w;
            }
        }
#pragma unroll
        for (int qr = 0; qr < QT; qr++) {
            float s = acc[qr] * 0.125f;
            if (causal && j > qt0 + qr) s -= 1e9f;
            sc[qr][j] = s;
        }
    }
    __syncthreads();

    {
        int warp = tid >> 5, lane = tid & 31;
        for (int qr = warp; qr < QT; qr += 4) {
            int qg = qt0 + qr;
            if (qg >= Sq) continue;
            float mx = -1e30f;
            for (int j = lane; j < Sk; j += 32) mx = fmaxf(mx, sc[qr][j]);
#pragma unroll
            for (int o = 16; o > 0; o >>= 1) mx = fmaxf(mx, __shfl_xor_sync(0xffffffffu, mx, o));
            float sum = 0.f;
            for (int j = lane; j < Sk; j += 32) {
                float e = __expf(sc[qr][j] - mx);
                sc[qr][j] = e;
                sum += e;
            }
#pragma unroll
            for (int o = 16; o > 0; o >>= 1) sum += __shfl_xor_sync(0xffffffffu, sum, o);
            float inv = 1.f / sum;
            for (int j = lane; j < Sk; j += 32) {
                float p = sc[qr][j] * inv;
                sc[qr][j] = p;
                if (attn_save)
                    attn_save[(((size_t)(b * HH + h)) * Sq + qg) * Sk + j] = p;
            }
        }
    }
    __syncthreads();

    {
        int gg = tid >> 6, d = tid & 63;
        float acc[QT];
#pragma unroll
        for (int qr = 0; qr < QT; qr++) acc[qr] = 0.f;
        for (int j = gg; j < Sk; j += 2) {
            float vv = v[((size_t)(b * Sk + j)) * ldv + h * DEPTH + d];
#pragma unroll
            for (int qr = 0; qr < QT; qr++) acc[qr] += sc[qr][j] * vv;
        }
#pragma unroll
        for (int qr = 0; qr < QT; qr++) pvs[gg][qr][d] = acc[qr];
    }
    __syncthreads();

    for (int e = tid; e < QT * DEPTH; e += 128) {
        int qr = e >> 6, d = e & 63;
        int qg = qt0 + qr;
        if (qg < Sq)
            out[((size_t)(b * Sq + qg)) * DD + h * DEPTH + d] = pvs[0][qr][d] + pvs[1][qr][d];
    }
}

// ---------------- in-place residual + LayerNorm ----------------
__global__ void __launch_bounds__(256) ln_kernel(
    float* __restrict__ x, const float* __restrict__ r,
    const float* __restrict__ g, const float* __restrict__ b)
{
    __shared__ float sm[8];
    __shared__ float bc;
    int row = blockIdx.x, tid = threadIdx.x;
    size_t base = (size_t)row * DD;
    float v0 = x[base + tid] + r[base + tid];
    float v1 = x[base + tid + 256] + r[base + tid + 256];
    float s = v0 + v1;
#pragma unroll
    for (int o = 16; o > 0; o >>= 1) s += __shfl_xor_sync(0xffffffffu, s, o);
    if ((tid & 31) == 0) sm[tid >> 5] = s;
    __syncthreads();
    if (tid == 0) {
        float t = 0.f;
        for (int w = 0; w < 8; w++) t += sm[w];
        bc = t * (1.0f / DD);
    }
    __syncthreads();
    float mean = bc;
    float d0 = v0 - mean, d1 = v1 - mean;
    float s2 = d0 * d0 + d1 * d1;
#pragma unroll
    for (int o = 16; o > 0; o >>= 1) s2 += __shfl_xor_sync(0xffffffffu, s2, o);
    if ((tid & 31) == 0) sm[tid >> 5] = s2;
    __syncthreads();
    if (tid == 0) {
        float t = 0.f;
        for (int w = 0; w < 8; w++) t += sm[w];
        bc = rsqrtf(t * (1.0f / DD) + 1e-6f);
    }
    __syncthreads();
    float inv = bc;
    x[base + tid]       = d0 * inv * g[tid]       + b[tid];
    x[base + tid + 256] = d1 * inv * g[tid + 256] + b[tid + 256];
}

// ---------------- tiled context ----------------
__global__ void __launch_bounds__(128) context_tile_kernel(
    const float* __restrict__ attn, const float* __restrict__ enc,
    float* __restrict__ ctx)
{
    __shared__ float at[QT][LIN];
    __shared__ float pvs[2][QT][DEPTH];

    int tt0 = blockIdx.x * QT, h = blockIdx.y, b = blockIdx.z;
    int tid = threadIdx.x;

    for (int e = tid; e < QT * LIN; e += 128) {
        int tr = e / LIN, l = e % LIN;
        int tg = tt0 + tr;
        at[tr][l] = (tg < TT)
            ? attn[(((size_t)(b * HH + h)) * TT + tg) * LIN + l] : 0.f;
    }
    __syncthreads();

    int g = tid >> 6, d = tid & 63;
    float acc[QT];
#pragma unroll
    for (int tr = 0; tr < QT; tr++) acc[tr] = 0.f;
    for (int l = g; l < LIN; l += 2) {
        float ev = enc[((size_t)(b * LIN + l)) * DD + h * DEPTH + d];
#pragma unroll
        for (int tr = 0; tr < QT; tr++) acc[tr] += at[tr][l] * ev;
    }
#pragma unroll
    for (int tr = 0; tr < QT; tr++) pvs[g][tr][d] = acc[tr];
    __syncthreads();

    for (int e = tid; e < QT * DEPTH; e += 128) {
        int tr = e >> 6, dd = e & 63;
        int tg = tt0 + tr;
        if (tg < TT)
            ctx[((size_t)(b * TT + tg)) * DD + h * DEPTH + dd] = pvs[0][tr][dd] + pvs[1][tr][dd];
    }
}

__global__ void __launch_bounds__(128) pgen_kernel(
    const float* __restrict__ ctx, const float* __restrict__ dec,
    const float* __restrict__ emb, const float* __restrict__ pw,
    const float* __restrict__ pb, float* __restrict__ pg)
{
    __shared__ float sm[4];
    int row = blockIdx.x, tid = threadIdx.x;
    size_t base = (size_t)row * DD;
    float s = 0.f;
    for (int d = tid; d < DD; d += 128)
        s += ctx[base + d] * pw[d] + dec[base + d] * pw[DD + d] + emb[base + d] * pw[2 * DD + d];
#pragma unroll
    for (int o = 16; o > 0; o >>= 1) s += __shfl_xor_sync(0xffffffffu, s, o);
    if ((tid & 31) == 0) sm[tid >> 5] = s;
    __syncthreads();
    if (tid == 0) {
        float t = sm[0] + sm[1] + sm[2] + sm[3] + pb[0] + pb[1] + pb[2];
        pg[row] = 1.0f / (1.0f + expf(-t));
    }
}

__global__ void attnmean_kernel(const float* __restrict__ b2, float* __restrict__ outm) {
    size_t i = (size_t)blockIdx.x * 256 + threadIdx.x;
    if (i >= (size_t)BT * LIN) return;
    int l = (int)(i % LIN);
    int t = (int)((i / LIN) % TT);
    int b = (int)(i / ((size_t)LIN * TT));
    float s = 0.f;
    for (int h = 0; h < HH; h++)
        s += b2[(((size_t)(b * HH + h)) * TT + t) * LIN + l];
    outm[i] = s * 0.125f;
}

__global__ void zerotail_kernel(float* __restrict__ out) {
    int i = blockIdx.x * 256 + threadIdx.x;
    if (i >= BT * OOV) return;
    int row = i / OOV, c = i % OOV;
    out[(size_t)row * VEXT + VV + c] = 0.f;
}

__global__ void scatter_kernel(const float* __restrict__ am, const float* __restrict__ pg,
                               const int* __restrict__ ext, float* __restrict__ out) {
    size_t i = (size_t)blockIdx.x * 256 + threadIdx.x;
    if (i >= (size_t)BT * LIN) return;
    int l = (int)(i % LIN);
    int t = (int)((i / LIN) % TT);
    int b = (int)(i / ((size_t)LIN * TT));
    int idx = ext[b * LIN + l];
    float val = (1.0f - pg[b * TT + t]) * am[i];
    atomicAdd(&out[((size_t)(b * TT) + t) * VEXT + idx], val);
}

// ---------------- host orchestration ----------------
static inline void gemm(const float* A, const float* W, const float* bias, float* C,
                        int M, int N, int K, int ldc, const float* rowScale, int relu) {
    dim3 grid(N / 128, (M + 63) / 64);
    gemm_tf32_kernel<<<grid, 256, GEMM_SMEM>>>(A, W, bias, C, M, N, K, ldc, rowScale, relu);
}

extern "C" void kernel_launch(void* const* d_in, const int* in_sizes, int n_in,
                              void* d_out, int out_size)
{
    const int* inp = (const int*)d_in[0];
    const int* tar = (const int*)d_in[1];
    const int* ext = (const int*)d_in[2];
    int wi = (in_sizes[6] == 1) ? 7 : 6;
    const float* emb_enc = (const float*)d_in[wi + 0];
    const float* emb_dec = (const float*)d_in[wi + 1];
    const float* eaw = (const float*)d_in[wi + 2];
    const float* eab = (const float*)d_in[wi + 3];
    const float* ew1 = (const float*)d_in[wi + 4];
    const float* eb1 = (const float*)d_in[wi + 5];
    const float* ew2 = (const float*)d_in[wi + 6];
    const float* eb2 = (const float*)d_in[wi + 7];
    const float* elg = (const float*)d_in[wi + 8];
    const float* elb = (const float*)d_in[wi + 9];
    const float* daw = (const float*)d_in[wi + 10];
    const float* dab = (const float*)d_in[wi + 11];
    const float* dw1 = (const float*)d_in[wi + 12];
    const float* db1 = (const float*)d_in[wi + 13];
    const float* dw2 = (const float*)d_in[wi + 14];
    const float* db2 = (const float*)d_in[wi + 15];
    const float* dlg = (const float*)d_in[wi + 16];
    const float* dlb = (const float*)d_in[wi + 17];
    const float* ptw = (const float*)d_in[wi + 18];
    const float* ptb = (const float*)d_in[wi + 19];
    const float* fw  = (const float*)d_in[wi + 20];
    const float* fb  = (const float*)d_in[wi + 21];
    float* out = (float*)d_out;

    cudaFuncSetAttribute(gemm_tf32_kernel,
                         cudaFuncAttributeMaxDynamicSharedMemorySize, GEMM_SMEM);

    float *xp, *qp, *ap, *bigp, *dxp, *t2p, *embp, *b2p, *ctxp, *pgp, *pep, *wpp;
    cudaGetSymbolAddress((void**)&xp,   g_x);
    cudaGetSymbolAddress((void**)&qp,   g_q);
    cudaGetSymbolAddress((void**)&ap,   g_a);
    cudaGetSymbolAddress((void**)&bigp, g_big);
    cudaGetSymbolAddress((void**)&dxp,  g_dx);
    cudaGetSymbolAddress((void**)&t2p,  g_t2);
    cudaGetSymbolAddress((void**)&embp, g_emb);
    cudaGetSymbolAddress((void**)&b2p,  g_b2);
    cudaGetSymbolAddress((void**)&ctxp, g_ctx);
    cudaGetSymbolAddress((void**)&pgp,  g_pg);
    cudaGetSymbolAddress((void**)&pep,  g_pe);
    cudaGetSymbolAddress((void**)&wpp,  g_wp);

    const size_t DD2 = (size_t)DD * DD;
    const int i_dec = NL - 1;

    pe_kernel<<<(LIN * DD + 255) / 256, 256>>>(pep);
    embed_enc_kernel<<<((size_t)BLIN * DD + 255) / 256, 256>>>(inp, emb_enc, pep, xp);
    pack_all_kernel<<<(11 * 512 * 512 + 255) / 256, 256>>>(eaw, daw, wpp);

    // ---------- encoder ----------
    for (int i = 0; i < NL; i++) {
        gemm(xp, wpp + (i == 0 ? WP_ENC0 : WP_ENC1), eab + (i * 4 + 0) * DD, bigp,
             BLIN, 1536, DD, 1536, nullptr, 0);
        attn_tile_kernel<<<dim3(LIN / QT, HH, BB), 128>>>(
            bigp, bigp + 512, bigp + 1024, ap, nullptr, LIN, LIN, 0, 1536, 1536, 1536);
        gemm(ap, eaw + (i * 4 + 3) * DD2, eab + (i * 4 + 3) * DD, qp, BLIN, DD, DD, DD, nullptr, 0);
        ln_kernel<<<BLIN, 256>>>(xp, qp, elg + (i * 2 + 0) * DD, elb + (i * 2 + 0) * DD);
        gemm(xp, ew1 + (size_t)i * DD * DFF, eb1 + i * DFF, bigp, BLIN, DFF, DD, DFF, nullptr, 1);
        gemm(bigp, ew2 + (size_t)i * DFF * DD, eb2 + i * DD, qp, BLIN, DD, DFF, DD, nullptr, 0);
        ln_kernel<<<BLIN, 256>>>(xp, qp, elg + (i * 2 + 1) * DD, elb + (i * 2 + 1) * DD);
    }
    // xp = enc_output

    // ---------- decoder (only last layer matters; reference never chains) --
    embed_dec_kernel<<<((size_t)BT * DD + 255) / 256, 256>>>(tar, emb_dec, pep, embp, dxp);
    {
        const int i = i_dec;
        const int TQ = (TT + QT - 1) / QT;
        gemm(dxp, wpp + WP_DSELF, dab + ((i * 2 + 0) * 4 + 0) * DD, bigp,
             BT, 1536, DD, 1536, nullptr, 0);
        attn_tile_kernel<<<dim3(TQ, HH, BB), 128>>>(
            bigp, bigp + 512, bigp + 1024, ap, nullptr, TT, TT, 1, 1536, 1536, 1536);
        gemm(ap, daw + ((i * 2 + 0) * 4 + 3) * DD2, dab + ((i * 2 + 0) * 4 + 3) * DD, t2p, BT, DD, DD, DD, nullptr, 0);
        ln_kernel<<<BT, 256>>>(dxp, t2p, dlg + (i * 3 + 0) * DD, dlb + (i * 3 + 0) * DD);  // o1
        gemm(dxp, daw + ((i * 2 + 1) * 4 + 0) * DD2, dab + ((i * 2 + 1) * 4 + 0) * DD, qp, BT, DD, DD, DD, nullptr, 0);
        gemm(xp, wpp + WP_DCROSS, dab + ((i * 2 + 1) * 4 + 1) * DD, bigp,
             BLIN, 1024, DD, 1024, nullptr, 0);
        attn_tile_kernel<<<dim3(TQ, HH, BB), 128>>>(
            qp, bigp, bigp + 512, ap, b2p, TT, LIN, 0, 512, 1024, 1024);
        gemm(ap, daw + ((i * 2 + 1) * 4 + 3) * DD2, dab + ((i * 2 + 1) * 4 + 3) * DD, t2p, BT, DD, DD, DD, nullptr, 0);
        ln_kernel<<<BT, 256>>>(dxp, t2p, dlg + (i * 3 + 1) * DD, dlb + (i * 3 + 1) * DD);  // o2
        gemm(dxp, dw1 + (size_t)i * DD * DFF, db1 + i * DFF, bigp, BT, DFF, DD, DFF, nullptr, 1);
        gemm(bigp, dw2 + (size_t)i * DFF * DD, db2 + i * DD, t2p, BT, DD, DFF, DD, nullptr, 0);
        ln_kernel<<<BT, 256>>>(dxp, t2p, dlg + (i * 3 + 2) * DD, dlb + (i * 3 + 2) * DD);  // dec_out
    }

    // ---------- pointer-generator head ----------
    const size_t OUT2 = (size_t)BT * VEXT;
    context_tile_kernel<<<dim3((TT + QT - 1) / QT, HH, BB), 128>>>(b2p, xp, ctxp);
    pgen_kernel<<<BT, 128>>>(ctxp, dxp, embp, ptw, ptb, pgp);
    attnmean_kernel<<<((size_t)BT * LIN + 255) / 256, 256>>>(b2p, out + OUT2);
    gemm(dxp, fw, fb, out, BT, VV, DD, VEXT, pgp, 0);
    zerotail_kernel<<<(BT * OOV + 255) / 256, 256>>>(out);
    scatter_kernel<<<((size_t)BT * LIN + 255) / 256, 256>>>(out + OUT2, pgp, ext, out);
}